// round 6
// baseline (speedup 1.0000x reference)
#include <cuda_runtime.h>
#include <cuda_bf16.h>

#define MAXN 100000
#define MAXE 1600000
#define DD   64
#define SCAN_T 1024

// Scratch (device globals — allocations forbidden).
__device__ int   g_cnt[MAXN];                 // in-degree (excl. self loop)
__device__ int   g_row[MAXN];                 // CSR row start
__device__ int   g_cur[MAXN];                 // fill cursor
__device__ float g_dinv[MAXN];                // deg^-1/2 (deg incl. self loop)
__device__ unsigned long long g_pairs[MAXE];  // packed (src, dinv[src])

// K1: zero histogram
__global__ void k_zero(int n) {
    int i = blockIdx.x * blockDim.x + threadIdx.x;
    if (i < n) g_cnt[i] = 0;
}

// K2: histogram of dst (RED.ADD, no return)
__global__ void k_count(const int* __restrict__ ei, int E) {
    int e = blockIdx.x * blockDim.x + threadIdx.x;
    if (e < E) atomicAdd(&g_cnt[ei[E + e]], 1);
}

// K3: single-block exclusive scan of g_cnt -> g_row/g_cur; dinv = rsqrt(cnt+1)
__global__ void k_scan(int n) {
    __shared__ int ssum[SCAN_T];
    int t = threadIdx.x;
    int chunk = (n + SCAN_T - 1) / SCAN_T;
    int beg = t * chunk;
    int end = min(beg + chunk, n);
    int s = 0;
    for (int i = beg; i < end; i++) s += g_cnt[i];
    ssum[t] = s;
    __syncthreads();
    for (int d = 1; d < SCAN_T; d <<= 1) {
        int v = (t >= d) ? ssum[t - d] : 0;
        __syncthreads();
        ssum[t] += v;
        __syncthreads();
    }
    int off = ssum[t] - s;
    for (int i = beg; i < end; i++) {
        int c = g_cnt[i];
        g_row[i] = off;
        g_cur[i] = off;
        g_dinv[i] = rsqrtf((float)(c + 1));
        off += c;
    }
}

// K4: CSR fill — pack (src, dinv[src]) per slot so the pull has no dependent
// dinv lookup.
__global__ void k_fill(const int* __restrict__ ei, int E) {
    int e = blockIdx.x * blockDim.x + threadIdx.x;
    if (e >= E) return;
    int s = ei[e];
    int d = ei[E + e];
    float w = __ldg(&g_dinv[s]);
    int pos = atomicAdd(&g_cur[d], 1);
    g_pairs[pos] = ((unsigned long long)(unsigned)__float_as_int(w) << 32)
                 | (unsigned)s;
}

// K5: fused pull + GEMM. One warp per node; lane owns 2 features (float2).
// Aggregate stays in registers; GEMM via shfl-broadcast against smem W^T.
__global__ void __launch_bounds__(256) k_fused(
    const float2* __restrict__ x2,
    const float* __restrict__ W,
    const float* __restrict__ b,
    float* __restrict__ out, int n)
{
    __shared__ float sWT[DD * DD];   // sWT[k*64 + j] = W[j*64 + k]
    // Coalesced smem stores, strided (sectorable) global reads of tiny W.
    for (int m = threadIdx.x; m < DD * DD; m += blockDim.x) {
        int k = m >> 6, j = m & 63;
        sWT[m] = W[j * DD + k];
    }
    __syncthreads();

    int wid  = threadIdx.x >> 5;
    int lane = threadIdx.x & 31;
    int node = blockIdx.x * 8 + wid;
    if (node >= n) return;

    float di = g_dinv[node];

    // self-loop: dinv^2 * x[node]
    float2 acc = __ldg(&x2[(size_t)node * 32 + lane]);
    float s2 = di * di;
    acc.x *= s2; acc.y *= s2;

    int beg = g_row[node];
    int cnt = g_cnt[node];
    int j = 0;
    for (; j + 4 <= cnt; j += 4) {
        // batch pair loads (broadcast across warp, L1-friendly)
        unsigned long long p0 = __ldg(&g_pairs[beg + j]);
        unsigned long long p1 = __ldg(&g_pairs[beg + j + 1]);
        unsigned long long p2 = __ldg(&g_pairs[beg + j + 2]);
        unsigned long long p3 = __ldg(&g_pairs[beg + j + 3]);
        int s0 = (int)(unsigned)p0, s1 = (int)(unsigned)p1;
        int s2i = (int)(unsigned)p2, s3 = (int)(unsigned)p3;
        // 4 independent row gathers in flight
        float2 v0 = __ldg(&x2[(size_t)s0 * 32 + lane]);
        float2 v1 = __ldg(&x2[(size_t)s1 * 32 + lane]);
        float2 v2 = __ldg(&x2[(size_t)s2i * 32 + lane]);
        float2 v3 = __ldg(&x2[(size_t)s3 * 32 + lane]);
        float n0 = di * __int_as_float((int)(p0 >> 32));
        float n1 = di * __int_as_float((int)(p1 >> 32));
        float n2 = di * __int_as_float((int)(p2 >> 32));
        float n3 = di * __int_as_float((int)(p3 >> 32));
        acc.x += n0 * v0.x + n1 * v1.x + n2 * v2.x + n3 * v3.x;
        acc.y += n0 * v0.y + n1 * v1.y + n2 * v2.y + n3 * v3.y;
    }
    for (; j < cnt; j++) {
        unsigned long long p0 = __ldg(&g_pairs[beg + j]);
        int s0 = (int)(unsigned)p0;
        float2 v0 = __ldg(&x2[(size_t)s0 * 32 + lane]);
        float n0 = di * __int_as_float((int)(p0 >> 32));
        acc.x += n0 * v0.x;
        acc.y += n0 * v0.y;
    }

    // GEMM: out[node][j] = b[j] + sum_k agg_k * W[j][k]
    // agg_k lives in lane (k>>1), component (k&1): broadcast via shfl.
    const float2* b2 = reinterpret_cast<const float2*>(b);
    float2 o = __ldg(&b2[lane]);
#pragma unroll
    for (int k = 0; k < DD; k++) {
        float a = __shfl_sync(0xffffffffu, (k & 1) ? acc.y : acc.x, k >> 1);
        float2 w = *reinterpret_cast<const float2*>(&sWT[k * DD + 2 * lane]);
        o.x += a * w.x;
        o.y += a * w.y;
    }
    reinterpret_cast<float2*>(out)[(size_t)node * 32 + lane] = o;
}

// ---------------------------------------------------------------------------
extern "C" void kernel_launch(void* const* d_in, const int* in_sizes, int n_in,
                              void* d_out, int out_size) {
    const float* x  = (const float*)d_in[0];
    const int*   ei = (const int*)d_in[1];
    const float* W  = (const float*)d_in[2];
    const float* b  = (const float*)d_in[3];
    float* out = (float*)d_out;

    int D = in_sizes[3];          // 64
    int n = in_sizes[0] / D;      // 100000
    int E = in_sizes[1] / 2;      // 1600000

    const int T = 256;
    k_zero <<<(n + T - 1) / T, T>>>(n);
    k_count<<<(E + T - 1) / T, T>>>(ei, E);
    k_scan <<<1, SCAN_T>>>(n);
    k_fill <<<(E + T - 1) / T, T>>>(ei, E);

    int blocks = (n + 7) / 8;     // one warp per node, 8 warps per block
    k_fused<<<blocks, 256>>>((const float2*)x, W, b, out, n);
}

// round 9
// speedup vs baseline: 1.4641x; 1.4641x over previous
#include <cuda_runtime.h>
#include <cuda_bf16.h>

#define MAXN 100000
#define MAXE 1600000
#define DD   64
#define SCAN_T 1024
#define GRP 8   // CSR slots merged per thread

// Scratch (device globals — allocations forbidden).
__device__ int   g_cnt[MAXN];
__device__ int   g_row[MAXN];
__device__ int   g_cur[MAXN];
__device__ float g_dinv[MAXN];
__device__ unsigned long long g_pairs[MAXE];  // (norm f32)<<32 | src
__device__ int   g_dst[MAXE];                 // dst per CSR slot
__device__ float g_agg[(size_t)MAXN * DD];

// K1: zero histogram
__global__ void k_zero(int n) {
    int i = blockIdx.x * blockDim.x + threadIdx.x;
    if (i < n) g_cnt[i] = 0;
}

// K2: int histogram of dst
__global__ void k_count(const int* __restrict__ ei, int E) {
    int e = blockIdx.x * blockDim.x + threadIdx.x;
    if (e < E) atomicAdd(&g_cnt[ei[E + e]], 1);
}

// K3: single-block exclusive scan -> g_row/g_cur; dinv = rsqrt(cnt+1)
__global__ void k_scan(int n) {
    __shared__ int ssum[SCAN_T];
    int t = threadIdx.x;
    int chunk = (n + SCAN_T - 1) / SCAN_T;
    int beg = t * chunk;
    int end = min(beg + chunk, n);
    int s = 0;
    for (int i = beg; i < end; i++) s += g_cnt[i];
    ssum[t] = s;
    __syncthreads();
    for (int d = 1; d < SCAN_T; d <<= 1) {
        int v = (t >= d) ? ssum[t - d] : 0;
        __syncthreads();
        ssum[t] += v;
        __syncthreads();
    }
    int off = ssum[t] - s;
    for (int i = beg; i < end; i++) {
        int c = g_cnt[i];
        g_row[i] = off;
        g_cur[i] = off;
        g_dinv[i] = rsqrtf((float)(c + 1));
        off += c;
    }
}

// K4: bucket fill — pack (norm, src); record dst per slot.
__global__ void k_fill(const int* __restrict__ ei, int E) {
    int e = blockIdx.x * blockDim.x + threadIdx.x;
    if (e >= E) return;
    int s = ei[e];
    int d = ei[E + e];
    float w = __ldg(&g_dinv[s]) * __ldg(&g_dinv[d]);
    int pos = atomicAdd(&g_cur[d], 1);
    g_pairs[pos] = ((unsigned long long)(unsigned)__float_as_int(w) << 32)
                 | (unsigned)s;
    g_dst[pos] = d;
}

// K5: agg[i,:] = x[i,:] * dinv[i]^2
__global__ void k_selfinit(const float4* __restrict__ x4, int n) {
    int idx = blockIdx.x * blockDim.x + threadIdx.x;
    if (idx >= n * (DD / 4)) return;
    int i = idx >> 4;
    float d = g_dinv[i];
    float s = d * d;
    float4 v = x4[idx];
    v.x *= s; v.y *= s; v.z *= s; v.w *= s;
    reinterpret_cast<float4*>(g_agg)[idx] = v;
}

__device__ __forceinline__ void red_v4(float* dst, float4 a) {
    asm volatile("red.global.add.v4.f32 [%0], {%1, %2, %3, %4};"
                 :: "l"(dst), "f"(a.x), "f"(a.y), "f"(a.z), "f"(a.w)
                 : "memory");
}

// K6: CSR-ordered scatter with register run-merging.
// Thread = (slot-group g of GRP consecutive slots, chunk c of 16).
// Slots of one dst are contiguous -> merge equal-dst runs in registers,
// flush one red.v4 per run instead of per slot.
__global__ void __launch_bounds__(256) k_scatter2(
    const float4* __restrict__ x4, int E)
{
    int gid = blockIdx.x * blockDim.x + threadIdx.x;
    int g = gid >> 4;
    int c = gid & 15;
    int base = g * GRP;
    if (base >= E) return;

    if (base + GRP <= E) {
        // fast path: full group, fully unrolled, 8 gathers in flight
        unsigned long long p[GRP];
        int ds[GRP];
#pragma unroll
        for (int i = 0; i < GRP; i++) p[i]  = __ldg(&g_pairs[base + i]);
#pragma unroll
        for (int i = 0; i < GRP; i++) ds[i] = __ldg(&g_dst[base + i]);
        float4 v[GRP];
#pragma unroll
        for (int i = 0; i < GRP; i++) {
            int s = (int)(unsigned)p[i];
            v[i] = __ldg(&x4[(size_t)s * 16 + c]);
        }
        float w0 = __int_as_float((int)(p[0] >> 32));
        float4 acc;
        acc.x = w0 * v[0].x; acc.y = w0 * v[0].y;
        acc.z = w0 * v[0].z; acc.w = w0 * v[0].w;
        int cur = ds[0];
#pragma unroll
        for (int i = 1; i < GRP; i++) {
            float w = __int_as_float((int)(p[i] >> 32));
            if (ds[i] == cur) {
                acc.x += w * v[i].x; acc.y += w * v[i].y;
                acc.z += w * v[i].z; acc.w += w * v[i].w;
            } else {
                red_v4(&g_agg[(size_t)cur * DD + c * 4], acc);
                acc.x = w * v[i].x; acc.y = w * v[i].y;
                acc.z = w * v[i].z; acc.w = w * v[i].w;
                cur = ds[i];
            }
        }
        red_v4(&g_agg[(size_t)cur * DD + c * 4], acc);
    } else {
        // tail group
        int m = E - base;
        unsigned long long p0 = __ldg(&g_pairs[base]);
        int s0 = (int)(unsigned)p0;
        float w0 = __int_as_float((int)(p0 >> 32));
        float4 v0 = __ldg(&x4[(size_t)s0 * 16 + c]);
        float4 acc;
        acc.x = w0 * v0.x; acc.y = w0 * v0.y;
        acc.z = w0 * v0.z; acc.w = w0 * v0.w;
        int cur = __ldg(&g_dst[base]);
        for (int i = 1; i < m; i++) {
            unsigned long long pi = __ldg(&g_pairs[base + i]);
            int si = (int)(unsigned)pi;
            float wi = __int_as_float((int)(pi >> 32));
            float4 vi = __ldg(&x4[(size_t)si * 16 + c]);
            int di = __ldg(&g_dst[base + i]);
            if (di == cur) {
                acc.x += wi * vi.x; acc.y += wi * vi.y;
                acc.z += wi * vi.z; acc.w += wi * vi.w;
            } else {
                red_v4(&g_agg[(size_t)cur * DD + c * 4], acc);
                acc.x = wi * vi.x; acc.y = wi * vi.y;
                acc.z = wi * vi.z; acc.w = wi * vi.w;
                cur = di;
            }
        }
        red_v4(&g_agg[(size_t)cur * DD + c * 4], acc);
    }
}

// K7: out = agg @ W^T + b (one node per thread, W^T in smem)
__global__ void k_gemm(const float* __restrict__ W,
                       const float* __restrict__ b,
                       float* __restrict__ out, int n) {
    __shared__ float sW[DD * DD];
    for (int idx = threadIdx.x; idx < DD * DD; idx += blockDim.x) {
        int j = idx >> 6, k = idx & 63;
        sW[k * DD + j] = W[idx];
    }
    __syncthreads();

    int node = blockIdx.x * blockDim.x + threadIdx.x;
    if (node >= n) return;

    float4 acc[16];
    const float4* b4 = reinterpret_cast<const float4*>(b);
#pragma unroll
    for (int jj = 0; jj < 16; jj++) acc[jj] = __ldg(&b4[jj]);

    const float4* a4 = reinterpret_cast<const float4*>(g_agg) + (size_t)node * 16;
#pragma unroll
    for (int kk = 0; kk < 16; kk++) {
        float4 av = a4[kk];
#pragma unroll
        for (int s = 0; s < 4; s++) {
            float v = (s == 0) ? av.x : (s == 1) ? av.y : (s == 2) ? av.z : av.w;
            const float4* wr = reinterpret_cast<const float4*>(&sW[(kk * 4 + s) * DD]);
#pragma unroll
            for (int jj = 0; jj < 16; jj++) {
                float4 w = wr[jj];
                acc[jj].x += v * w.x;
                acc[jj].y += v * w.y;
                acc[jj].z += v * w.z;
                acc[jj].w += v * w.w;
            }
        }
    }

    float4* o4 = reinterpret_cast<float4*>(out) + (size_t)node * 16;
#pragma unroll
    for (int jj = 0; jj < 16; jj++) o4[jj] = acc[jj];
}

// ---------------------------------------------------------------------------
extern "C" void kernel_launch(void* const* d_in, const int* in_sizes, int n_in,
                              void* d_out, int out_size) {
    const float* x  = (const float*)d_in[0];
    const int*   ei = (const int*)d_in[1];
    const float* W  = (const float*)d_in[2];
    const float* b  = (const float*)d_in[3];
    float* out = (float*)d_out;

    int D = in_sizes[3];          // 64
    int n = in_sizes[0] / D;      // 100000
    int E = in_sizes[1] / 2;      // 1600000

    const int T = 256;
    k_zero <<<(n + T - 1) / T, T>>>(n);
    k_count<<<(E + T - 1) / T, T>>>(ei, E);
    k_scan <<<1, SCAN_T>>>(n);
    k_fill <<<(E + T - 1) / T, T>>>(ei, E);

    int self_work = n * (D / 4);
    k_selfinit<<<(self_work + T - 1) / T, T>>>((const float4*)x, n);

    int groups = (E + GRP - 1) / GRP;
    long long sc_threads = (long long)groups * 16;
    int sc_blocks = (int)((sc_threads + T - 1) / T);
    k_scatter2<<<sc_blocks, T>>>((const float4*)x, E);

    k_gemm<<<(n + T - 1) / T, T>>>(W, b, out, n);
}

// round 10
// speedup vs baseline: 2.6170x; 1.7875x over previous
#include <cuda_runtime.h>
#include <cuda_bf16.h>

#define MAXN 100000
#define MAXE 1600000
#define DD   64

// Scratch (device globals — allocations forbidden).
__device__ float g_deg[MAXN];                // degree -> dinv in place
__device__ int4  g_edge16[MAXE];             // {src, dst, norm_bits, pad}
__device__ float g_agg[(size_t)MAXN * DD];   // aggregated rows (25.6 MB)

// ---------------------------------------------------------------------------
__global__ void k_init_deg(int n) {
    int i = blockIdx.x * blockDim.x + threadIdx.x;
    if (i < n) g_deg[i] = 1.0f;
}

__global__ void k_count(const int* __restrict__ ei, int E) {
    int e = blockIdx.x * blockDim.x + threadIdx.x;
    if (e < E) atomicAdd(&g_deg[ei[E + e]], 1.0f);
}

__global__ void k_dinv(int n) {
    int i = blockIdx.x * blockDim.x + threadIdx.x;
    if (i < n) g_deg[i] = rsqrtf(g_deg[i]);
}

// Precompute per-edge record: one 16B coalesced store; scatter gets everything
// with a single broadcast LDG.128.
__global__ void k_pairs(const int* __restrict__ ei, int E) {
    int e = blockIdx.x * blockDim.x + threadIdx.x;
    if (e >= E) return;
    int s = ei[e];
    int d = ei[E + e];
    float nrm = __ldg(&g_deg[s]) * __ldg(&g_deg[d]);
    g_edge16[e] = make_int4(s, d, __float_as_int(nrm), 0);
}

// agg[i,:] = x[i,:] * dinv[i]^2  (self loop)
__global__ void k_selfinit(const float4* __restrict__ x4, int n) {
    int idx = blockIdx.x * blockDim.x + threadIdx.x;
    if (idx >= n * (DD / 4)) return;
    int i = idx >> 4;
    float d = g_deg[i];
    float s = d * d;
    float4 v = x4[idx];
    v.x *= s; v.y *= s; v.z *= s; v.w *= s;
    reinterpret_cast<float4*>(g_agg)[idx] = v;
}

__device__ __forceinline__ void red_v4(float* dst, float4 a) {
    asm volatile("red.global.add.v4.f32 [%0], {%1, %2, %3, %4};"
                 :: "l"(dst), "f"(a.x), "f"(a.y), "f"(a.z), "f"(a.w)
                 : "memory");
}

// Edge scatter: 16 threads/edge, each one float4 chunk. Minimal instruction
// stream: 1 broadcast LDG.128 + 1 gather LDG.128 + 1 red.v4.
__global__ void __launch_bounds__(256) k_scatter(
    const float4* __restrict__ x4, int E)
{
    long long idx = (long long)blockIdx.x * blockDim.x + threadIdx.x;
    if (idx >= (long long)E * 16) return;
    int e = (int)(idx >> 4);
    int c = (int)(idx & 15);
    int4 p = __ldg(&g_edge16[e]);
    float4 v = __ldg(&x4[(size_t)p.x * 16 + c]);
    float w = __int_as_float(p.z);
    v.x *= w; v.y *= w; v.z *= w; v.w *= w;
    red_v4(&g_agg[(size_t)p.y * DD + c * 4], v);
}

// ---------------------------------------------------------------------------
// Packed f32x2 helpers (B300: fma.rn.f32x2 — 2 FMA per instruction)
__device__ __forceinline__ unsigned long long pk2(float lo, float hi) {
    unsigned long long r;
    asm("mov.b64 %0, {%1, %2};" : "=l"(r) : "f"(lo), "f"(hi));
    return r;
}
__device__ __forceinline__ float2 upk2(unsigned long long v) {
    float2 t;
    asm("mov.b64 {%0, %1}, %2;" : "=f"(t.x), "=f"(t.y) : "l"(v));
    return t;
}
__device__ __forceinline__ unsigned long long fma2(
    unsigned long long a, unsigned long long b, unsigned long long c) {
    unsigned long long r;
    asm("fma.rn.f32x2 %0, %1, %2, %3;" : "=l"(r) : "l"(a), "l"(b), "l"(c));
    return r;
}

// GEMM: out = agg @ W^T + b. Two threads per node (32 outputs each),
// FFMA2 inner loop against smem-staged W^T.
__global__ void __launch_bounds__(256) k_gemm(
    const float* __restrict__ W,
    const float* __restrict__ b,
    float* __restrict__ out, int n)
{
    __shared__ float sWT[DD * DD];   // sWT[k*64 + j] = W[j*64 + k]
    for (int m = threadIdx.x; m < DD * DD; m += blockDim.x) {
        int j = m >> 6, k = m & 63;
        sWT[k * DD + j] = W[m];
    }
    __syncthreads();

    int t = blockIdx.x * blockDim.x + threadIdx.x;
    int node = t >> 1;
    int half = t & 1;
    if (node >= n) return;

    // 16 packed accumulators = 32 outputs [half*32, half*32+32)
    unsigned long long acc2[16];
    const unsigned long long* b2 = reinterpret_cast<const unsigned long long*>(b);
#pragma unroll
    for (int m = 0; m < 16; m++) acc2[m] = __ldg(&b2[half * 16 + m]);

    const float4* a4 = reinterpret_cast<const float4*>(g_agg) + (size_t)node * 16;
#pragma unroll
    for (int kk = 0; kk < 16; kk++) {
        float4 av = a4[kk];
#pragma unroll
        for (int s = 0; s < 4; s++) {
            float a = (s == 0) ? av.x : (s == 1) ? av.y : (s == 2) ? av.z : av.w;
            unsigned long long a2 = pk2(a, a);
            const unsigned long long* wr = reinterpret_cast<const unsigned long long*>(
                &sWT[(kk * 4 + s) * DD + half * 32]);
#pragma unroll
            for (int m = 0; m < 16; m++)
                acc2[m] = fma2(a2, wr[m], acc2[m]);
        }
    }

    float4* o4 = reinterpret_cast<float4*>(out) + (size_t)node * 16 + half * 8;
#pragma unroll
    for (int m = 0; m < 8; m++) {
        float2 lo = upk2(acc2[2 * m]);
        float2 hi = upk2(acc2[2 * m + 1]);
        o4[m] = make_float4(lo.x, lo.y, hi.x, hi.y);
    }
}

// ---------------------------------------------------------------------------
extern "C" void kernel_launch(void* const* d_in, const int* in_sizes, int n_in,
                              void* d_out, int out_size) {
    const float* x  = (const float*)d_in[0];
    const int*   ei = (const int*)d_in[1];
    const float* W  = (const float*)d_in[2];
    const float* b  = (const float*)d_in[3];
    float* out = (float*)d_out;

    int D = in_sizes[3];          // 64
    int n = in_sizes[0] / D;      // 100000
    int E = in_sizes[1] / 2;      // 1600000

    const int T = 256;
    k_init_deg<<<(n + T - 1) / T, T>>>(n);
    k_count   <<<(E + T - 1) / T, T>>>(ei, E);
    k_dinv    <<<(n + T - 1) / T, T>>>(n);
    k_pairs   <<<(E + T - 1) / T, T>>>(ei, E);

    int self_work = n * (D / 4);
    k_selfinit<<<(self_work + T - 1) / T, T>>>((const float4*)x, n);

    long long sc = (long long)E * 16;
    int sc_blocks = (int)((sc + T - 1) / T);
    k_scatter <<<sc_blocks, T>>>((const float4*)x, E);

    int gemm_threads = n * 2;
    k_gemm    <<<(gemm_threads + T - 1) / T, T>>>(W, b, out, n);
}

// round 11
// speedup vs baseline: 3.3062x; 1.2634x over previous
#include <cuda_runtime.h>
#include <cuda_bf16.h>

#define MAXN 100000
#define MAXE 1600000
#define DD   64

// Scratch (device globals — allocations forbidden).
__device__ float g_deg[MAXN];                // raw degree (incl. self loop)
__device__ float g_dinv[MAXN];               // deg^-1/2
__device__ float g_agg[(size_t)MAXN * DD];   // aggregated rows (25.6 MB)

// ---------------------------------------------------------------------------
__global__ void k_init_deg(int n) {
    int i = blockIdx.x * blockDim.x + threadIdx.x;
    if (i < n) g_deg[i] = 1.0f;
}

__global__ void k_count(const int* __restrict__ ei, int E) {
    int e = blockIdx.x * blockDim.x + threadIdx.x;
    if (e < E) atomicAdd(&g_deg[ei[E + e]], 1.0f);
}

// agg[i,:] = x[i,:] * (1/deg[i]); also publishes dinv = rsqrt(deg) to g_dinv.
// Reads raw g_deg, writes separate g_dinv -> no intra-kernel race.
__global__ void k_selfinit(const float4* __restrict__ x4, int n) {
    int idx = blockIdx.x * blockDim.x + threadIdx.x;
    if (idx >= n * (DD / 4)) return;
    int i = idx >> 4;
    float d = rsqrtf(g_deg[i]);
    if ((idx & 15) == 0) g_dinv[i] = d;
    float s = d * d;
    float4 v = x4[idx];
    v.x *= s; v.y *= s; v.z *= s; v.w *= s;
    reinterpret_cast<float4*>(g_agg)[idx] = v;
}

// Edge scatter (R1-proven shape): 16 threads/edge, one float4 chunk each.
__global__ void k_scatter(const float4* __restrict__ x4,
                          const int* __restrict__ ei, int E) {
    long long idx = (long long)blockIdx.x * blockDim.x + threadIdx.x;
    if (idx >= (long long)E * (DD / 4)) return;
    int e = (int)(idx >> 4);
    int c = (int)(idx & 15);
    int s  = __ldg(&ei[e]);
    int dt = __ldg(&ei[E + e]);
    float nrm = __ldg(&g_dinv[s]) * __ldg(&g_dinv[dt]);
    float4 v = __ldg(&x4[(size_t)s * (DD / 4) + c]);
    v.x *= nrm; v.y *= nrm; v.z *= nrm; v.w *= nrm;
    float* dst = &g_agg[(size_t)dt * DD + c * 4];
    asm volatile("red.global.add.v4.f32 [%0], {%1, %2, %3, %4};"
                 :: "l"(dst), "f"(v.x), "f"(v.y), "f"(v.z), "f"(v.w)
                 : "memory");
}

// ---------------------------------------------------------------------------
// Packed f32x2 helpers (B300 FFMA2 — only reachable via PTX fma.rn.f32x2)
__device__ __forceinline__ unsigned long long pk2(float lo, float hi) {
    unsigned long long r;
    asm("mov.b64 %0, {%1, %2};" : "=l"(r) : "f"(lo), "f"(hi));
    return r;
}
__device__ __forceinline__ float2 upk2(unsigned long long v) {
    float2 t;
    asm("mov.b64 {%0, %1}, %2;" : "=f"(t.x), "=f"(t.y) : "l"(v));
    return t;
}
__device__ __forceinline__ unsigned long long fma2(
    unsigned long long a, unsigned long long b, unsigned long long c) {
    unsigned long long r;
    asm("fma.rn.f32x2 %0, %1, %2, %3;" : "=l"(r) : "l"(a), "l"(b), "l"(c));
    return r;
}

// GEMM: out = agg @ W^T + b. One node per thread (R1 structure), FFMA2 core.
// acc2[m] packs outputs {2m, 2m+1}; weight pairs read from smem as u64.
__global__ void k_gemm(const float* __restrict__ W,
                       const float* __restrict__ b,
                       float* __restrict__ out, int n) {
    __shared__ float sWT[DD * DD];   // sWT[k*64 + j] = W[j*64 + k]
    for (int idx = threadIdx.x; idx < DD * DD; idx += blockDim.x) {
        int j = idx >> 6, k = idx & 63;
        sWT[k * DD + j] = W[idx];
    }
    __syncthreads();

    int node = blockIdx.x * blockDim.x + threadIdx.x;
    if (node >= n) return;

    unsigned long long acc2[32];     // 64 outputs as 32 f32x2 pairs
    const unsigned long long* b2 = reinterpret_cast<const unsigned long long*>(b);
#pragma unroll
    for (int m = 0; m < 32; m++) acc2[m] = __ldg(&b2[m]);

    const float4* a4 = reinterpret_cast<const float4*>(g_agg) + (size_t)node * 16;
#pragma unroll
    for (int kk = 0; kk < 16; kk++) {
        float4 av = a4[kk];
#pragma unroll
        for (int s = 0; s < 4; s++) {
            float a = (s == 0) ? av.x : (s == 1) ? av.y : (s == 2) ? av.z : av.w;
            unsigned long long a2 = pk2(a, a);
            const unsigned long long* wr = reinterpret_cast<const unsigned long long*>(
                &sWT[(kk * 4 + s) * DD]);
#pragma unroll
            for (int m = 0; m < 32; m++)
                acc2[m] = fma2(a2, wr[m], acc2[m]);
        }
    }

    float4* o4 = reinterpret_cast<float4*>(out) + (size_t)node * 16;
#pragma unroll
    for (int m = 0; m < 16; m++) {
        float2 lo = upk2(acc2[2 * m]);
        float2 hi = upk2(acc2[2 * m + 1]);
        o4[m] = make_float4(lo.x, lo.y, hi.x, hi.y);
    }
}

// ---------------------------------------------------------------------------
extern "C" void kernel_launch(void* const* d_in, const int* in_sizes, int n_in,
                              void* d_out, int out_size) {
    const float* x  = (const float*)d_in[0];
    const int*   ei = (const int*)d_in[1];
    const float* W  = (const float*)d_in[2];
    const float* b  = (const float*)d_in[3];
    float* out = (float*)d_out;

    int D = in_sizes[3];          // 64
    int n = in_sizes[0] / D;      // 100000
    int E = in_sizes[1] / 2;      // 1600000

    const int T = 256;
    k_init_deg<<<(n + T - 1) / T, T>>>(n);
    k_count   <<<(E + T - 1) / T, T>>>(ei, E);

    int self_work = n * (D / 4);
    k_selfinit<<<(self_work + T - 1) / T, T>>>((const float4*)x, n);

    long long sc = (long long)E * (D / 4);
    int sc_blocks = (int)((sc + T - 1) / T);
    k_scatter <<<sc_blocks, T>>>((const float4*)x, ei, E);

    k_gemm    <<<(n + T - 1) / T, T>>>(W, b, out, n);
}

// round 12
// speedup vs baseline: 3.4750x; 1.0511x over previous
#include <cuda_runtime.h>
#include <cuda_bf16.h>

#define MAXN 100000
#define MAXE 1600000
#define DD   64
#define ALLOC_T 1024

// Scratch (device globals — allocations forbidden).
__device__ int   g_cnt[MAXN];                // in-degree (excl. self loop)
__device__ int   g_cur[MAXN];                // bucket cursor (starts at base)
__device__ float g_dinv[MAXN];               // (deg incl self)^-1/2
__device__ int   g_total;                    // bucket allocator
__device__ int4  g_rec[MAXE];                // {src, dst, w_bits, 0}, dst-bucketed
__device__ float g_agg[(size_t)MAXN * DD];   // aggregated rows (25.6 MB)

// K1: zero histogram + allocator
__global__ void k_init(int n) {
    int i = blockIdx.x * blockDim.x + threadIdx.x;
    if (i < n) g_cnt[i] = 0;
    if (i == 0) g_total = 0;
}

// K2: int histogram of dst
__global__ void k_count(const int* __restrict__ ei, int E) {
    int e = blockIdx.x * blockDim.x + threadIdx.x;
    if (e < E) atomicAdd(&g_cnt[ei[E + e]], 1);
}

// K3: scan-free bucket allocation. Block-level scan of counts, one global
// atomic per block for the base. Also computes dinv = rsqrt(cnt+1).
__global__ void __launch_bounds__(ALLOC_T) k_alloc(int n) {
    int i = blockIdx.x * ALLOC_T + threadIdx.x;
    int lane = threadIdx.x & 31;
    int wid  = threadIdx.x >> 5;
    int c = (i < n) ? g_cnt[i] : 0;

    // inclusive warp scan
    int s = c;
#pragma unroll
    for (int d = 1; d < 32; d <<= 1) {
        int v = __shfl_up_sync(0xffffffffu, s, d);
        if (lane >= d) s += v;
    }

    __shared__ int wsum[32];
    __shared__ int blockbase;
    if (lane == 31) wsum[wid] = s;
    __syncthreads();
    if (wid == 0) {
        int ws = (lane < (ALLOC_T / 32)) ? wsum[lane] : 0;
#pragma unroll
        for (int d = 1; d < 32; d <<= 1) {
            int v = __shfl_up_sync(0xffffffffu, ws, d);
            if (lane >= d) ws += v;
        }
        wsum[lane] = ws;                       // inclusive scan of warp sums
        if (lane == 31) blockbase = atomicAdd(&g_total, ws);
    }
    __syncthreads();
    if (i < n) {
        int prev = (wid > 0) ? wsum[wid - 1] : 0;
        g_cur[i]  = blockbase + prev + (s - c);   // bucket base for node i
        g_dinv[i] = rsqrtf((float)(c + 1));
    }
}

// K4: fill dst-buckets with full edge records (w precomputed once per edge).
__global__ void k_fill(const int* __restrict__ ei, int E) {
    int e = blockIdx.x * blockDim.x + threadIdx.x;
    if (e >= E) return;
    int s = ei[e];
    int d = ei[E + e];
    float w = __ldg(&g_dinv[s]) * __ldg(&g_dinv[d]);
    int pos = atomicAdd(&g_cur[d], 1);
    g_rec[pos] = make_int4(s, d, __float_as_int(w), 0);
}

// K5: agg[i,:] = x[i,:] * dinv[i]^2 (self loop; also resets agg every replay)
__global__ void k_selfinit(const float4* __restrict__ x4, int n) {
    int idx = blockIdx.x * blockDim.x + threadIdx.x;
    if (idx >= n * (DD / 4)) return;
    int i = idx >> 4;
    float d = g_dinv[i];
    float s = d * d;
    float4 v = x4[idx];
    v.x *= s; v.y *= s; v.z *= s; v.w *= s;
    reinterpret_cast<float4*>(g_agg)[idx] = v;
}

__device__ __forceinline__ void red_v4(float* dst, float4 a) {
    asm volatile("red.global.add.v4.f32 [%0], {%1, %2, %3, %4};"
                 :: "l"(dst), "f"(a.x), "f"(a.y), "f"(a.z), "f"(a.w)
                 : "memory");
}
__device__ __forceinline__ void facc(float4& a, float4 v, float w) {
    a.x += w * v.x; a.y += w * v.y; a.z += w * v.z; a.w += w * v.w;
}
__device__ __forceinline__ float4 fmul(float4 v, float w) {
    return make_float4(w * v.x, w * v.y, w * v.z, w * v.w);
}

// K6: merged scatter. Group = 4 consecutive bucket slots x 16 feature chunks.
// Bit-reversed group mapping de-clusters same-address atomics in time
// (adjacent-in-time groups are >=2^17 slots apart; same-bucket groups are
// >=2^17 apart in execution order >> residency window).
__global__ void __launch_bounds__(256) k_scatter4(
    const float4* __restrict__ x4, int E, int kbits, int ngroups)
{
    int gid  = blockIdx.x * blockDim.x + threadIdx.x;
    int glin = gid >> 4;
    int c    = gid & 15;
    int gp   = (int)(__brev((unsigned)glin) >> (32 - kbits));
    if (gp >= ngroups) return;
    int base = gp * 4;

    if (base + 4 <= E) {
        int4 r0 = __ldg(&g_rec[base + 0]);
        int4 r1 = __ldg(&g_rec[base + 1]);
        int4 r2 = __ldg(&g_rec[base + 2]);
        int4 r3 = __ldg(&g_rec[base + 3]);
        float4 m0 = __ldg(&x4[(size_t)r0.x * 16 + c]);
        float4 m1 = __ldg(&x4[(size_t)r1.x * 16 + c]);
        float4 m2 = __ldg(&x4[(size_t)r2.x * 16 + c]);
        float4 m3 = __ldg(&x4[(size_t)r3.x * 16 + c]);
        float w0 = __int_as_float(r0.z), w1 = __int_as_float(r1.z);
        float w2 = __int_as_float(r2.z), w3 = __int_as_float(r3.z);

        float4 acc = fmul(m0, w0);
        int cur = r0.y;
        if (r1.y == cur) facc(acc, m1, w1);
        else { red_v4(&g_agg[(size_t)cur * DD + c * 4], acc); acc = fmul(m1, w1); cur = r1.y; }
        if (r2.y == cur) facc(acc, m2, w2);
        else { red_v4(&g_agg[(size_t)cur * DD + c * 4], acc); acc = fmul(m2, w2); cur = r2.y; }
        if (r3.y == cur) facc(acc, m3, w3);
        else { red_v4(&g_agg[(size_t)cur * DD + c * 4], acc); acc = fmul(m3, w3); cur = r3.y; }
        red_v4(&g_agg[(size_t)cur * DD + c * 4], acc);
    } else {
        // tail group (E % 4 != 0)
        int m = E - base;
        int4 r0 = __ldg(&g_rec[base]);
        float4 acc = fmul(__ldg(&x4[(size_t)r0.x * 16 + c]), __int_as_float(r0.z));
        int cur = r0.y;
        for (int j = 1; j < m; j++) {
            int4 rj = __ldg(&g_rec[base + j]);
            float4 vj = __ldg(&x4[(size_t)rj.x * 16 + c]);
            float wj = __int_as_float(rj.z);
            if (rj.y == cur) facc(acc, vj, wj);
            else { red_v4(&g_agg[(size_t)cur * DD + c * 4], acc); acc = fmul(vj, wj); cur = rj.y; }
        }
        red_v4(&g_agg[(size_t)cur * DD + c * 4], acc);
    }
}

// ---------------------------------------------------------------------------
// Packed f32x2 helpers (B300 FFMA2 via PTX)
__device__ __forceinline__ unsigned long long pk2(float lo, float hi) {
    unsigned long long r;
    asm("mov.b64 %0, {%1, %2};" : "=l"(r) : "f"(lo), "f"(hi));
    return r;
}
__device__ __forceinline__ float2 upk2(unsigned long long v) {
    float2 t;
    asm("mov.b64 {%0, %1}, %2;" : "=f"(t.x), "=f"(t.y) : "l"(v));
    return t;
}
__device__ __forceinline__ unsigned long long fma2(
    unsigned long long a, unsigned long long b, unsigned long long c) {
    unsigned long long r;
    asm("fma.rn.f32x2 %0, %1, %2, %3;" : "=l"(r) : "l"(a), "l"(b), "l"(c));
    return r;
}

// K7: out = agg @ W^T + b (one node per thread, FFMA2 core — R11-proven)
__global__ void k_gemm(const float* __restrict__ W,
                       const float* __restrict__ b,
                       float* __restrict__ out, int n) {
    __shared__ float sWT[DD * DD];   // sWT[k*64 + j] = W[j*64 + k]
    for (int idx = threadIdx.x; idx < DD * DD; idx += blockDim.x) {
        int j = idx >> 6, k = idx & 63;
        sWT[k * DD + j] = W[idx];
    }
    __syncthreads();

    int node = blockIdx.x * blockDim.x + threadIdx.x;
    if (node >= n) return;

    unsigned long long acc2[32];
    const unsigned long long* b2 = reinterpret_cast<const unsigned long long*>(b);
#pragma unroll
    for (int m = 0; m < 32; m++) acc2[m] = __ldg(&b2[m]);

    const float4* a4 = reinterpret_cast<const float4*>(g_agg) + (size_t)node * 16;
#pragma unroll
    for (int kk = 0; kk < 16; kk++) {
        float4 av = a4[kk];
#pragma unroll
        for (int s = 0; s < 4; s++) {
            float a = (s == 0) ? av.x : (s == 1) ? av.y : (s == 2) ? av.z : av.w;
            unsigned long long a2 = pk2(a, a);
            const unsigned long long* wr = reinterpret_cast<const unsigned long long*>(
                &sWT[(kk * 4 + s) * DD]);
#pragma unroll
            for (int m = 0; m < 32; m++)
                acc2[m] = fma2(a2, wr[m], acc2[m]);
        }
    }

    float4* o4 = reinterpret_cast<float4*>(out) + (size_t)node * 16;
#pragma unroll
    for (int m = 0; m < 16; m++) {
        float2 lo = upk2(acc2[2 * m]);
        float2 hi = upk2(acc2[2 * m + 1]);
        o4[m] = make_float4(lo.x, lo.y, hi.x, hi.y);
    }
}

// ---------------------------------------------------------------------------
extern "C" void kernel_launch(void* const* d_in, const int* in_sizes, int n_in,
                              void* d_out, int out_size) {
    const float* x  = (const float*)d_in[0];
    const int*   ei = (const int*)d_in[1];
    const float* W  = (const float*)d_in[2];
    const float* b  = (const float*)d_in[3];
    float* out = (float*)d_out;

    int D = in_sizes[3];          // 64
    int n = in_sizes[0] / D;      // 100000
    int E = in_sizes[1] / 2;      // 1600000

    const int T = 256;
    k_init <<<(n + T - 1) / T, T>>>(n);
    k_count<<<(E + T - 1) / T, T>>>(ei, E);
    k_alloc<<<(n + ALLOC_T - 1) / ALLOC_T, ALLOC_T>>>(n);
    k_fill <<<(E + T - 1) / T, T>>>(ei, E);

    int self_work = n * (D / 4);
    k_selfinit<<<(self_work + T - 1) / T, T>>>((const float4*)x, n);

    int ngroups = (E + 3) / 4;
    int kbits = 0;
    while ((1 << kbits) < ngroups) kbits++;
    long long sc = (long long)(1 << kbits) * 16;
    int sc_blocks = (int)((sc + T - 1) / T);
    k_scatter4<<<sc_blocks, T>>>((const float4*)x, E, kbits, ngroups);

    k_gemm<<<(n + T - 1) / T, T>>>(W, b, out, n);
}

// round 16
// speedup vs baseline: 3.6981x; 1.0642x over previous
#include <cuda_runtime.h>
#include <cuda_bf16.h>

#define MAXN 100000
#define MAXE 1600000
#define DD   64
#define ALLOC_T 1024
#define GRP 8

// Scratch (device globals — allocations forbidden).
__device__ int   g_cnt[MAXN];                  // in-degree (excl. self loop)
__device__ int   g_cur[MAXN];                  // bucket cursor
__device__ float g_dinv[MAXN];                 // (deg incl self)^-1/2
__device__ int   g_total;                      // bucket allocator
__device__ unsigned long long g_rec[MAXE];     // src | dst<<32, dst-bucketed
__device__ float g_agg[(size_t)MAXN * DD];     // aggregated rows (25.6 MB)

// K1: zero histogram + allocator
__global__ void k_init(int n) {
    int i = blockIdx.x * blockDim.x + threadIdx.x;
    if (i < n) g_cnt[i] = 0;
    if (i == 0) g_total = 0;
}

// K2: int histogram of dst
__global__ void k_count(const int* __restrict__ ei, int E) {
    int e = blockIdx.x * blockDim.x + threadIdx.x;
    if (e < E) atomicAdd(&g_cnt[ei[E + e]], 1);
}

// K3: scan-free bucket allocation (block scan + one global atomic per block);
// also dinv = rsqrt(cnt+1).
__global__ void __launch_bounds__(ALLOC_T) k_alloc(int n) {
    int i = blockIdx.x * ALLOC_T + threadIdx.x;
    int lane = threadIdx.x & 31;
    int wid  = threadIdx.x >> 5;
    int c = (i < n) ? g_cnt[i] : 0;

    int s = c;
#pragma unroll
    for (int d = 1; d < 32; d <<= 1) {
        int v = __shfl_up_sync(0xffffffffu, s, d);
        if (lane >= d) s += v;
    }

    __shared__ int wsum[32];
    __shared__ int blockbase;
    if (lane == 31) wsum[wid] = s;
    __syncthreads();
    if (wid == 0) {
        int ws = (lane < (ALLOC_T / 32)) ? wsum[lane] : 0;
#pragma unroll
        for (int d = 1; d < 32; d <<= 1) {
            int v = __shfl_up_sync(0xffffffffu, ws, d);
            if (lane >= d) ws += v;
        }
        wsum[lane] = ws;
        if (lane == 31) blockbase = atomicAdd(&g_total, ws);
    }
    __syncthreads();
    if (i < n) {
        int prev = (wid > 0) ? wsum[wid - 1] : 0;
        g_cur[i]  = blockbase + prev + (s - c);
        g_dinv[i] = rsqrtf((float)(c + 1));
    }
}

// K4: fill dst-buckets with packed (src, dst) — no dinv reads, 8B store.
__global__ void k_fill(const int* __restrict__ ei, int E) {
    int e = blockIdx.x * blockDim.x + threadIdx.x;
    if (e >= E) return;
    int s = ei[e];
    int d = ei[E + e];
    int pos = atomicAdd(&g_cur[d], 1);
    g_rec[pos] = (unsigned)s | ((unsigned long long)(unsigned)d << 32);
}

// K5: agg[i,:] = x[i,:] * dinv[i]^2 (self loop; resets agg every replay)
__global__ void k_selfinit(const float4* __restrict__ x4, int n) {
    int idx = blockIdx.x * blockDim.x + threadIdx.x;
    if (idx >= n * (DD / 4)) return;
    int i = idx >> 4;
    float d = g_dinv[i];
    float s = d * d;
    float4 v = x4[idx];
    v.x *= s; v.y *= s; v.z *= s; v.w *= s;
    reinterpret_cast<float4*>(g_agg)[idx] = v;
}

__device__ __forceinline__ void red_v4(float* dst, float4 a) {
    asm volatile("red.global.add.v4.f32 [%0], {%1, %2, %3, %4};"
                 :: "l"(dst), "f"(a.x), "f"(a.y), "f"(a.z), "f"(a.w)
                 : "memory");
}
__device__ __forceinline__ void facc(float4& a, float4 v, float w) {
    a.x += w * v.x; a.y += w * v.y; a.z += w * v.z; a.w += w * v.w;
}
__device__ __forceinline__ float4 fmul(float4 v, float w) {
    return make_float4(w * v.x, w * v.y, w * v.z, w * v.w);
}

// K6: merged scatter, GRP=8 bucket slots x 16 feature chunks per thread.
// Bit-reversed group order de-clusters same-address atomics in time.
// dinv lookups here are warp-deduplicated (16 lanes share addresses).
__global__ void __launch_bounds__(256) k_scatter8(
    const float4* __restrict__ x4, int E, int kbits, int ngroups)
{
    int gid  = blockIdx.x * blockDim.x + threadIdx.x;
    int glin = gid >> 4;
    int c    = gid & 15;
    int gp   = (int)(__brev((unsigned)glin) >> (32 - kbits));
    if (gp >= ngroups) return;
    int base = gp * GRP;

    if (base + GRP <= E) {
        unsigned long long r[GRP];
#pragma unroll
        for (int i = 0; i < GRP; i++) r[i] = __ldg(&g_rec[base + i]);
        int s[GRP], d[GRP];
#pragma unroll
        for (int i = 0; i < GRP; i++) {
            s[i] = (int)(unsigned)r[i];
            d[i] = (int)(unsigned)(r[i] >> 32);
        }
        float4 v[GRP];
#pragma unroll
        for (int i = 0; i < GRP; i++) v[i] = __ldg(&x4[(size_t)s[i] * 16 + c]);
        float w[GRP];
#pragma unroll
        for (int i = 0; i < GRP; i++)
            w[i] = __ldg(&g_dinv[s[i]]) * __ldg(&g_dinv[d[i]]);

        float4 acc = fmul(v[0], w[0]);
        int cur = d[0];
#pragma unroll
        for (int i = 1; i < GRP; i++) {
            if (d[i] == cur) facc(acc, v[i], w[i]);
            else {
                red_v4(&g_agg[(size_t)cur * DD + c * 4], acc);
                acc = fmul(v[i], w[i]);
                cur = d[i];
            }
        }
        red_v4(&g_agg[(size_t)cur * DD + c * 4], acc);
    } else {
        int m = E - base;
        unsigned long long r0 = __ldg(&g_rec[base]);
        int s0 = (int)(unsigned)r0;
        int cur = (int)(unsigned)(r0 >> 32);
        float w0 = __ldg(&g_dinv[s0]) * __ldg(&g_dinv[cur]);
        float4 acc = fmul(__ldg(&x4[(size_t)s0 * 16 + c]), w0);
        for (int j = 1; j < m; j++) {
            unsigned long long rj = __ldg(&g_rec[base + j]);
            int sj = (int)(unsigned)rj;
            int dj = (int)(unsigned)(rj >> 32);
            float wj = __ldg(&g_dinv[sj]) * __ldg(&g_dinv[dj]);
            float4 vj = __ldg(&x4[(size_t)sj * 16 + c]);
            if (dj == cur) facc(acc, vj, wj);
            else {
                red_v4(&g_agg[(size_t)cur * DD + c * 4], acc);
                acc = fmul(vj, wj);
                cur = dj;
            }
        }
        red_v4(&g_agg[(size_t)cur * DD + c * 4], acc);
    }
}

// ---------------------------------------------------------------------------
// Packed f32x2 helpers (B300 FFMA2 via PTX)
__device__ __forceinline__ unsigned long long pk2(float lo, float hi) {
    unsigned long long r;
    asm("mov.b64 %0, {%1, %2};" : "=l"(r) : "f"(lo), "f"(hi));
    return r;
}
__device__ __forceinline__ float2 upk2(unsigned long long v) {
    float2 t;
    asm("mov.b64 {%0, %1}, %2;" : "=f"(t.x), "=f"(t.y) : "l"(v));
    return t;
}
__device__ __forceinline__ unsigned long long fma2(
    unsigned long long a, unsigned long long b, unsigned long long c) {
    unsigned long long r;
    asm("fma.rn.f32x2 %0, %1, %2, %3;" : "=l"(r) : "l"(a), "l"(b), "l"(c));
    return r;
}

// K7: out = agg @ W^T + b (one node per thread, FFMA2 core)
__global__ void k_gemm(const float* __restrict__ W,
                       const float* __restrict__ b,
                       float* __restrict__ out, int n) {
    __shared__ float sWT[DD * DD];   // sWT[k*64 + j] = W[j*64 + k]
    for (int idx = threadIdx.x; idx < DD * DD; idx += blockDim.x) {
        int j = idx >> 6, k = idx & 63;
        sWT[k * DD + j] = W[idx];
    }
    __syncthreads();

    int node = blockIdx.x * blockDim.x + threadIdx.x;
    if (node >= n) return;

    unsigned long long acc2[32];
    const unsigned long long* b2 = reinterpret_cast<const unsigned long long*>(b);
#pragma unroll
    for (int m = 0; m < 32; m++) acc2[m] = __ldg(&b2[m]);

    const float4* a4 = reinterpret_cast<const float4*>(g_agg) + (size_t)node * 16;
#pragma unroll
    for (int kk = 0; kk < 16; kk++) {
        float4 av = a4[kk];
#pragma unroll
        for (int s = 0; s < 4; s++) {
            float a = (s == 0) ? av.x : (s == 1) ? av.y : (s == 2) ? av.z : av.w;
            unsigned long long a2 = pk2(a, a);
            const unsigned long long* wr = reinterpret_cast<const unsigned long long*>(
                &sWT[(kk * 4 + s) * DD]);
#pragma unroll
            for (int m = 0; m < 32; m++)
                acc2[m] = fma2(a2, wr[m], acc2[m]);
        }
    }

    float4* o4 = reinterpret_cast<float4*>(out) + (size_t)node * 16;
#pragma unroll
    for (int m = 0; m < 16; m++) {
        float2 lo = upk2(acc2[2 * m]);
        float2 hi = upk2(acc2[2 * m + 1]);
        o4[m] = make_float4(lo.x, lo.y, hi.x, hi.y);
    }
}

// ---------------------------------------------------------------------------
extern "C" void kernel_launch(void* const* d_in, const int* in_sizes, int n_in,
                              void* d_out, int out_size) {
    const float* x  = (const float*)d_in[0];
    const int*   ei = (const int*)d_in[1];
    const float* W  = (const float*)d_in[2];
    const float* b  = (const float*)d_in[3];
    float* out = (float*)d_out;

    int D = in_sizes[3];          // 64
    int n = in_sizes[0] / D;      // 100000
    int E = in_sizes[1] / 2;      // 1600000

    const int T = 256;
    k_init <<<(n + T - 1) / T, T>>>(n);
    k_count<<<(E + T - 1) / T, T>>>(ei, E);
    k_alloc<<<(n + ALLOC_T - 1) / ALLOC_T, ALLOC_T>>>(n);
    k_fill <<<(E + T - 1) / T, T>>>(ei, E);

    int self_work = n * (D / 4);
    k_selfinit<<<(self_work + T - 1) / T, T>>>((const float4*)x, n);

    int ngroups = (E + GRP - 1) / GRP;
    int kbits = 0;
    while ((1 << kbits) < ngroups) kbits++;
    long long sc = (long long)(1 << kbits) * 16;
    int sc_blocks = (int)((sc + T - 1) / T);
    k_scatter8<<<sc_blocks, T>>>((const float4*)x, E, kbits, ngroups);

    k_gemm<<<(n + T - 1) / T, T>>>(W, b, out, n);
}